// round 2
// baseline (speedup 1.0000x reference)
#include <cuda_runtime.h>
#include <cuda_bf16.h>
#include <math_constants.h>

// Problem constants (fixed shapes)
#define BB 64
#define LL 512
#define HH 768
#define TT 9

__device__ float g_llh[BB];
__device__ float g_logits_scratch[BB * LL * TT];   // fallback if out has no room

// ---------------------------------------------------------------------------
// Kernel A: logits = hidden @ W + b
// warp computes 4 rows; hidden loaded coalesced from gmem, W from smem
// (layout Ws[k*9+t] -> lane stride 9 words, conflict-free).
// ---------------------------------------------------------------------------
__global__ __launch_bounds__(256) void logits_kernel(
    const float* __restrict__ hidden,
    const float* __restrict__ W,
    const float* __restrict__ bias,
    float* __restrict__ logits)
{
    __shared__ float Ws[HH * TT];   // 6912 floats = 27648 B
    __shared__ float bs[TT];

    for (int i = threadIdx.x; i < HH * TT; i += blockDim.x) Ws[i] = W[i];
    if (threadIdx.x < TT) bs[threadIdx.x] = bias[threadIdx.x];
    __syncthreads();

    const int lane   = threadIdx.x & 31;
    const int gwarp  = (blockIdx.x * blockDim.x + threadIdx.x) >> 5;
    const int nwarps = (gridDim.x * blockDim.x) >> 5;
    const int nrows  = BB * LL;   // 32768

    for (int rb = gwarp * 4; rb < nrows; rb += nwarps * 4) {
        float acc[4][TT];
        #pragma unroll
        for (int r = 0; r < 4; r++)
            #pragma unroll
            for (int t = 0; t < TT; t++) acc[r][t] = 0.f;

        const float* h0 = hidden + (size_t)rb * HH;

        #pragma unroll 4
        for (int k0 = 0; k0 < HH; k0 += 32) {
            int k = k0 + lane;
            float h[4];
            #pragma unroll
            for (int r = 0; r < 4; r++) h[r] = h0[r * HH + k];
            #pragma unroll
            for (int t = 0; t < TT; t++) {
                float w = Ws[k * TT + t];
                #pragma unroll
                for (int r = 0; r < 4; r++) acc[r][t] = fmaf(h[r], w, acc[r][t]);
            }
        }

        // butterfly reduce each of the 36 partials across the warp
        #pragma unroll
        for (int r = 0; r < 4; r++)
            #pragma unroll
            for (int t = 0; t < TT; t++)
                #pragma unroll
                for (int off = 16; off > 0; off >>= 1)
                    acc[r][t] += __shfl_xor_sync(0xffffffffu, acc[r][t], off);

        #pragma unroll
        for (int r = 0; r < 4; r++) {
            if (lane == r) {
                float* o = logits + (size_t)(rb + r) * TT;
                #pragma unroll
                for (int t = 0; t < TT; t++) o[t] = acc[r][t] + bs[t];
            }
        }
    }
}

// ---------------------------------------------------------------------------
// Kernel B: per-batch CRF numerator + forward-algorithm denominator.
// One block per batch element. Warp 0: sequential LSE scan (lanes 0..8 hold
// the score vector). Warp 1: numerator via parallel label gather.
// NOTE: labels buffer is int32 (JAX default x64-disabled downcasts int64).
// ---------------------------------------------------------------------------
__global__ __launch_bounds__(128) void crf_kernel(
    const float* __restrict__ logits,
    const int*   __restrict__ mask,
    const int*   __restrict__ labels,
    const float* __restrict__ start_trans,
    const float* __restrict__ end_trans,
    const float* __restrict__ trans)
{
    __shared__ float e_s[LL * TT];   // 18432 B
    __shared__ float m_s[LL];
    __shared__ int   lab_s[LL];
    __shared__ float tr_s[TT * TT];
    __shared__ float num_sh;

    const int b   = blockIdx.x;
    const int tid = threadIdx.x;
    const int lane = tid & 31;
    const int warp = tid >> 5;

    const float* lg = logits + (size_t)b * LL * TT;
    for (int i = tid; i < LL * TT; i += blockDim.x) e_s[i] = lg[i];
    for (int i = tid; i < LL; i += blockDim.x) {
        int l = labels[(size_t)b * LL + i];
        lab_s[i] = (l == -100) ? 0 : l;
        m_s[i]   = (float)mask[(size_t)b * LL + i];
    }
    if (tid < TT * TT) tr_s[tid] = trans[tid];
    __syncthreads();

    // ---- numerator (warp 1) ----
    if (warp == 1) {
        float acc = 0.f;
        int   msum = 0;
        for (int t = lane; t < LL; t += 32) {
            msum += (m_s[t] != 0.f) ? 1 : 0;
            if (t >= 1) {
                int lp = lab_s[t - 1], lt = lab_s[t];
                acc = fmaf(tr_s[lp * TT + lt] + e_s[t * TT + lt], m_s[t], acc);
            }
        }
        #pragma unroll
        for (int off = 16; off > 0; off >>= 1) {
            acc  += __shfl_xor_sync(0xffffffffu, acc, off);
            msum += __shfl_xor_sync(0xffffffffu, msum, off);
        }
        if (lane == 0) {
            int seq_end = msum - 1;
            if (seq_end < 0) seq_end = 0;
            int l0 = lab_s[0];
            int llast = lab_s[seq_end];
            num_sh = start_trans[l0] + e_s[l0] + acc + end_trans[llast];
        }
    }

    // ---- denominator scan (warp 0) ----
    float denom = 0.f;
    if (warp == 0) {
        const int j = (lane < TT) ? lane : (TT - 1);
        float trc[TT];
        #pragma unroll
        for (int k = 0; k < TT; k++) trc[k] = tr_s[k * TT + j];

        float score = start_trans[j] + e_s[j];

        const float L2E = 1.4426950408889634f;
        const float LN2 = 0.6931471805599453f;

        for (int t = 1; t < LL; t++) {
            float e  = e_s[t * TT + j];
            float ms = m_s[t];

            float v[TT];
            #pragma unroll
            for (int k = 0; k < TT; k++)
                v[k] = __shfl_sync(0xffffffffu, score, k) + trc[k];

            float m01 = fmaxf(v[0], v[1]);
            float m23 = fmaxf(v[2], v[3]);
            float m45 = fmaxf(v[4], v[5]);
            float m67 = fmaxf(v[6], v[7]);
            float m = fmaxf(fmaxf(fmaxf(m01, m23), fmaxf(m45, m67)), v[8]);

            float s = 0.f;
            #pragma unroll
            for (int k = 0; k < TT; k++)
                s += exp2f((v[k] - m) * L2E);

            float nxt = fmaf(__log2f(s), LN2, m) + e;
            score = (ms != 0.f) ? nxt : score;
        }

        // denom = LSE_j(score[j] + end_trans[j])
        float fv = (lane < TT) ? score + end_trans[lane] : -CUDART_INF_F;
        float mm = fv;
        #pragma unroll
        for (int off = 16; off > 0; off >>= 1)
            mm = fmaxf(mm, __shfl_xor_sync(0xffffffffu, mm, off));
        float ss = (lane < TT) ? exp2f((fv - mm) * L2E) : 0.f;
        #pragma unroll
        for (int off = 16; off > 0; off >>= 1)
            ss += __shfl_xor_sync(0xffffffffu, ss, off);
        denom = fmaf(__log2f(ss), LN2, mm);
    }

    __syncthreads();   // num_sh ready
    if (warp == 0 && lane == 0)
        g_llh[b] = num_sh - denom;
}

// ---------------------------------------------------------------------------
// Kernel C: loss = -mean(llh), deterministic tree reduce
// ---------------------------------------------------------------------------
__global__ void loss_kernel(float* __restrict__ loss_out)
{
    int lane = threadIdx.x;   // 32 threads
    float v = g_llh[lane] + g_llh[lane + 32];
    #pragma unroll
    for (int off = 16; off > 0; off >>= 1)
        v += __shfl_xor_sync(0xffffffffu, v, off);
    if (lane == 0) loss_out[0] = -v * (1.0f / (float)BB);
}

// tiny helper to fetch the scratch pointer on host (no alloc, just symbol addr)
__global__ void noop_kernel() {}

// ---------------------------------------------------------------------------
extern "C" void kernel_launch(void* const* d_in, const int* in_sizes, int n_in,
                              void* d_out, int out_size)
{
    const float* hidden      = (const float*)d_in[0];
    const int*   attn_mask   = (const int*)d_in[1];
    const int*   labels      = (const int*)d_in[2];   // int32 (JAX x64 disabled)
    const float* W           = (const float*)d_in[3];
    const float* bias        = (const float*)d_in[4];
    const float* start_trans = (const float*)d_in[5];
    const float* end_trans   = (const float*)d_in[6];
    const float* trans       = (const float*)d_in[7];

    float* out = (float*)d_out;

    // Resolve scratch symbol address (host-side, no allocation)
    static float* scratch = nullptr;
    if (!scratch) {
        void* p = nullptr;
        cudaGetSymbolAddress(&p, g_logits_scratch);
        scratch = (float*)p;
    }

    const int NLOG = BB * LL * TT;   // 294912
    float* loss_ptr;
    float* logits_ptr;
    if (out_size >= NLOG + 1) {          // (loss, logits) concatenated
        loss_ptr   = out;
        logits_ptr = out + 1;
    } else if (out_size == NLOG) {       // logits only
        loss_ptr   = scratch;            // harmless parking spot
        logits_ptr = out;
    } else {                             // loss only
        loss_ptr   = out;
        logits_ptr = scratch;
    }

    logits_kernel<<<1024, 256>>>(hidden, W, bias, logits_ptr);
    crf_kernel<<<BB, 128>>>(logits_ptr, attn_mask, labels,
                            start_trans, end_trans, trans);
    loss_kernel<<<1, 32>>>(loss_ptr);
}